// round 3
// baseline (speedup 1.0000x reference)
#include <cuda_runtime.h>

// RNNEncoder: 2-layer GRU, H=64, N=512 seqs (B=16 x C=32), L=2048, scalar input layer0.
// Persistent kernel: 128 CTAs x 4 seqs, 576 threads (9 roles x 64 j).
// Weights in registers (1 row / thread), h in shared, packed fma.rn.f32x2 math.
// Layer-1 pipelined one step behind layer-0 -> single dot phase, 2 barriers/step.

#define LSEQ 2048
#define HD 64
#define CCH 32
#define SEQ_PER_CTA 4
#define NTHREADS 576

typedef unsigned long long u64;

__device__ __forceinline__ u64 pk(float x, float y) {
    u64 r; asm("mov.b64 %0, {%1,%2};" : "=l"(r) : "f"(x), "f"(y)); return r;
}
__device__ __forceinline__ void upk(u64 v, float& x, float& y) {
    asm("mov.b64 {%0,%1}, %2;" : "=f"(x), "=f"(y) : "l"(v));
}
__device__ __forceinline__ u64 fma2(u64 a, u64 b, u64 c) {
    u64 d; asm("fma.rn.f32x2 %0, %1, %2, %3;" : "=l"(d) : "l"(a), "l"(b), "l"(c)); return d;
}

__device__ __forceinline__ float sigf(float x) {
    return __fdividef(1.f, 1.f + __expf(-x));
}
// tanh(x) = 2*sigmoid(2x) - 1  (exact identity; __expf err ~2ulp)
__device__ __forceinline__ float tanh_fast(float x) {
    return fmaf(2.f, __fdividef(1.f, 1.f + __expf(-2.f * x)), -1.f);
}

__global__ void __launch_bounds__(NTHREADS, 1) gru2_kernel(
    const float* __restrict__ x,
    const float* __restrict__ w_ih0, const float* __restrict__ w_hh0,
    const float* __restrict__ b0,    const float* __restrict__ bn0,
    const float* __restrict__ w_ih1, const float* __restrict__ w_hh1,
    const float* __restrict__ b1,    const float* __restrict__ bn1,
    float* __restrict__ out)
{
    __shared__ __align__(16) float h0sh[SEQ_PER_CTA][HD];
    __shared__ __align__(16) float h1sh[SEQ_PER_CTA][HD];
    __shared__ __align__(16) float stage[9][SEQ_PER_CTA][HD];
    __shared__ float xsh[SEQ_PER_CTA][LSEQ];

    const int tid  = threadIdx.x;
    const int role = tid >> 6;          // 0..8
    const int j    = tid & 63;
    // role 0..2: W_hh0 gate g, reads h0 ; role 3..5: W_hh1 gate g, reads h1 ;
    // role 6..8: W_ih1 gate g, reads h0 (layer-1 input gemm)
    const int g = (role >= 6) ? (role - 6) : ((role >= 3) ? (role - 3) : role);
    const float* mat = (role < 3) ? w_hh0 : ((role < 6) ? w_hh1 : w_ih1);
    const float* row = mat + (g * HD + j) * HD;

    // weight row in registers as 32 packed f32x2
    u64 wr[32];
#pragma unroll
    for (int i = 0; i < 32; i++) wr[i] = ((const u64*)row)[i];
    const float biasc = (role >= 6) ? b1[g * HD + j] : 0.f;

    // combine-phase per-j constants
    const float c_wir = w_ih0[j],        c_wiz = w_ih0[HD + j],  c_win = w_ih0[2 * HD + j];
    const float c_br  = b0[j],           c_bz  = b0[HD + j],     c_bn  = b0[2 * HD + j];
    const float c_bnn0 = bn0[j],         c_bnn1 = bn1[j];

    // stage x for this CTA's 4 sequences into shared
    const int nbase = blockIdx.x * SEQ_PER_CTA;
    for (int i = tid; i < SEQ_PER_CTA * LSEQ; i += NTHREADS) {
        int s = i >> 11, t = i & (LSEQ - 1);
        int n = nbase + s;
        int b = n >> 5, c = n & (CCH - 1);
        xsh[s][t] = x[(size_t)b * LSEQ * CCH + (size_t)t * CCH + c];
    }
    if (tid < SEQ_PER_CTA * HD)            ((float*)h0sh)[tid]       = 0.f;
    else if (tid < 2 * SEQ_PER_CTA * HD)   ((float*)h1sh)[tid - 256] = 0.f;
    __syncthreads();

    for (int u = 0; u <= LSEQ; ++u) {
        // ---- Phase A: all 9 dot-rows, sequences in 2 pairs (reg-pressure relief) ----
        const float* hb = (role >= 3 && role < 6) ? &h1sh[0][0] : &h0sh[0][0];
#pragma unroll
        for (int p = 0; p < 2; ++p) {
            u64 a0 = 0ull, a1 = 0ull;
            const float* hA = hb + (2 * p + 0) * HD;
            const float* hB = hb + (2 * p + 1) * HD;
#pragma unroll
            for (int i = 0; i < 16; i++) {
                float4 v0 = ((const float4*)hA)[i];
                float4 v1 = ((const float4*)hB)[i];
                u64 w0 = wr[2 * i], w1 = wr[2 * i + 1];
                a0 = fma2(w0, pk(v0.x, v0.y), a0); a0 = fma2(w1, pk(v0.z, v0.w), a0);
                a1 = fma2(w0, pk(v1.x, v1.y), a1); a1 = fma2(w1, pk(v1.z, v1.w), a1);
            }
            float lo, hi;
            upk(a0, lo, hi); stage[role][2 * p + 0][j] = lo + hi + biasc;
            upk(a1, lo, hi); stage[role][2 * p + 1][j] = lo + hi + biasc;
        }
        __syncthreads();

        // ---- Phase B: gate combines (layer0 for step u, layer1 for step u-1) ----
        if (tid < 256) {               // layer-0 combine, s = role
            if (u < LSEQ) {
                int s = role;
                float xv = xsh[s][u];
                float r  = sigf(fmaf(c_wir, xv, c_br) + stage[0][s][j]);
                float z  = sigf(fmaf(c_wiz, xv, c_bz) + stage[1][s][j]);
                float nn = tanh_fast(fmaf(c_win, xv, c_bn) + r * (stage[2][s][j] + c_bnn0));
                float h  = h0sh[s][j];
                h0sh[s][j] = nn + z * (h - nn);
            }
        } else if (tid < 512) {        // layer-1 combine, s = role-4
            if (u >= 1) {
                int s = role - 4;
                float r  = sigf(stage[6][s][j] + stage[3][s][j]);
                float z  = sigf(stage[7][s][j] + stage[4][s][j]);
                float nn = tanh_fast(stage[8][s][j] + r * (stage[5][s][j] + c_bnn1));
                float h  = h1sh[s][j];
                float hn = nn + z * (h - nn);
                h1sh[s][j] = hn;
                out[(size_t)(nbase + s) * LSEQ * HD + (size_t)(u - 1) * HD + j] = hn;
            }
        }
        __syncthreads();
    }
}

extern "C" void kernel_launch(void* const* d_in, const int* in_sizes, int n_in,
                              void* d_out, int out_size) {
    const float* x     = (const float*)d_in[0];
    const float* w_ih0 = (const float*)d_in[1];
    const float* w_hh0 = (const float*)d_in[2];
    const float* b0    = (const float*)d_in[3];
    const float* bn0   = (const float*)d_in[4];
    const float* w_ih1 = (const float*)d_in[5];
    const float* w_hh1 = (const float*)d_in[6];
    const float* b1    = (const float*)d_in[7];
    const float* bn1   = (const float*)d_in[8];
    float* out = (float*)d_out;

    gru2_kernel<<<128, NTHREADS>>>(x, w_ih0, w_hh0, b0, bn0,
                                   w_ih1, w_hh1, b1, bn1, out);
}